// round 17
// baseline (speedup 1.0000x reference)
#include <cuda_runtime.h>
#include <cstdint>

#define B_  8
#define H_  128
#define W_  128
#define C_  64
#define F_  128

#define SB    136   // B smem stride: banks (tc*8+g) -> conflict-free frags
#define SAM   36    // A smem stride, m-major (32 k + 4 pad) -> banks 4g+tc
#define BBUF  (32*SB)                       // 4352 floats
#define ABUFM (128*SAM)                     // 4608 floats

// scratch
__device__ float  g_wTp[18*BBUF];           // w_out tf32, pre-padded [ch][kk*SB+n]
__device__ float2 g_wOff2[3*3*64*10];       // w_off as oc-pairs [dydx][c][10]
__device__ float4 g_xT[B_*16*H_*W_];        // x channel-blocked [b][c/4][y][x]

__device__ __forceinline__ uint32_t f2tf32(float f){
    uint32_t r; asm("cvt.rna.tf32.f32 %0, %1;" : "=r"(r) : "f"(f)); return r;
}
__device__ __forceinline__ unsigned long long pack2(float x, float y){
    unsigned long long r;
    asm("mov.b64 %0, {%1,%2};" : "=l"(r) : "f"(x), "f"(y));
    return r;
}
__device__ __forceinline__ void ffma2(unsigned long long& acc,
                                      unsigned long long a, unsigned long long w){
    asm("fma.rn.f32x2 %0, %1, %2, %0;" : "+l"(acc) : "l"(a), "l"(w));
}
__device__ __forceinline__ void addf2(unsigned long long& acc, unsigned long long v){
    asm("add.rn.f32x2 %0, %1, %2;" : "=l"(acc) : "l"(acc), "l"(v));
}
__device__ __forceinline__ uint32_t smem_u32(const void* p){
    uint32_t a;
    asm("{ .reg .u64 t; cvta.to.shared.u64 t, %1; cvt.u32.u64 %0, t; }":"=r"(a):"l"(p));
    return a;
}
__device__ __forceinline__ void cpasync16(uint32_t dst, const void* src){
    asm volatile("cp.async.cg.shared.global [%0], [%1], 16;"::"r"(dst),"l"(src):"memory");
}
#define CP_COMMIT() asm volatile("cp.async.commit_group;":::"memory")
#define CP_WAIT0()  asm volatile("cp.async.wait_group 0;":::"memory")

__device__ __forceinline__ void mma_tf32(float* d, const uint32_t* a, const uint32_t* bb){
    asm volatile(
      "mma.sync.aligned.m16n8k8.row.col.f32.tf32.tf32.f32 "
      "{%0,%1,%2,%3}, {%4,%5,%6,%7}, {%8,%9}, {%0,%1,%2,%3};"
      : "+f"(d[0]),"+f"(d[1]),"+f"(d[2]),"+f"(d[3])
      : "r"(a[0]),"r"(a[1]),"r"(a[2]),"r"(a[3]),"r"(bb[0]),"r"(bb[1]));
}

// ---------------------------------------------------------------------------
// Fused prep kernel (unchanged content)
// ---------------------------------------------------------------------------
__global__ __launch_bounds__(256) void prep_fused(
    const float* __restrict__ w_out, const float* __restrict__ w_off,
    const float4* __restrict__ x4)
{
    const int blk = blockIdx.x;
    const int tid = threadIdx.x;
    if (blk < 1024) {                       // transpose x
        const int px   = tid & 127;
        const int half = tid >> 7;
        const int b = blk >> 7, y = blk & 127;
        const int pix16 = (blk * 128 + px) * 16;
        #pragma unroll
        for (int qq = 0; qq < 8; qq++) {
            int cb = half * 8 + qq;
            g_xT[((b*16 + cb) << 14) + y*128 + px] = x4[pix16 + cb];
        }
    } else if (blk < 1024 + 306) {          // w_out -> padded tf32
        int idx = (blk - 1024) * 256 + tid;
        int n  = idx % SB;
        int kk = (idx / SB) & 31;
        int ch = idx / BBUF;
        float v = 0.f;
        if (n < 128) v = __uint_as_float(f2tf32(w_out[(ch*32 + kk)*128 + n]));
        g_wTp[idx] = v;
    } else {                                // w_off -> oc-pairs
        int idx = (blk - 1330) * 256 + tid;
        if (idx < 5760) {
            int p    = idx % 10;
            int c    = (idx / 10) % 64;
            int dydx = idx / 640;
            float2 v = make_float2(0.f, 0.f);
            if (p < 9) {
                v.x = w_off[(dydx*64 + c)*18 + 2*p];
                v.y = w_off[(dydx*64 + c)*18 + 2*p + 1];
            }
            g_wOff2[idx] = v;
        }
    }
}

// ---------------------------------------------------------------------------
// FUSED kernel. Phase 1 writes offsets to SMEM (no gmem round-trip).
// Phase 2: A tile m-major (STS.128), tf32 mma GEMM.
// SMEM: A0 A1 (4608 ea) | B0 B1 (4352 ea) | off_sh (2304) = 20224 fl = 80896B
// ---------------------------------------------------------------------------
#define ROWF   (130*66)
#define WSLICE (3*64*10)
#define OFF_SH_OFF (2*ABUFM + 2*BBUF)       // 17920 floats
#define SM2_TOTAL ((OFF_SH_OFF + 2304) * 4) // 80896 B -> 2 blocks/SM

__global__ __launch_bounds__(256, 2) void dconv_fused(
    const float* __restrict__ x, const float* __restrict__ b_off,
    const float* __restrict__ b_out, float* __restrict__ out)
{
    extern __shared__ float sm[];
    float* off_sh = sm + OFF_SH_OFF;        // [128][18]

    const int tid = threadIdx.x;
    const int by  = blockIdx.x;             // b*128 + y

    // ======================= PHASE 1: offset conv =======================
    {
        float* row = sm;                                         // [130][66]
        unsigned long long* wsh = (unsigned long long*)(sm + ROWF);

        const int pms = tid & 127;
        const int sth = tid >> 7;
        const int s   = tid & 31;
        const int q   = tid >> 5;
        const int b   = by >> 7;
        const int y   = by & 127;

        unsigned long long acc1[4][9];
        #pragma unroll
        for (int p = 0; p < 9; p++) {
            unsigned long long bz = (q == 0) ? pack2(b_off[2*p], b_off[2*p+1])
                                             : pack2(0.f, 0.f);
            #pragma unroll
            for (int r = 0; r < 4; r++) acc1[r][p] = bz;
        }

        for (int dy = 0; dy < 3; dy++) {
            __syncthreads();
            const int yy = y + dy - 1;
            {
                const unsigned long long* src =
                    (const unsigned long long*)g_wOff2 + dy * WSLICE;
                for (int i = tid; i < WSLICE; i += 256) wsh[i] = src[i];
            }
            if (tid < 2) {
                const int e = (tid == 0) ? 0 : 129;
                float2* z = (float2*)&row[e * 66];
                #pragma unroll
                for (int i = 0; i < 32; i++) z[i] = make_float2(0.f, 0.f);
            }
            {
                float2* dst = (float2*)&row[(pms + 1) * 66] + sth * 16;
                if (yy >= 0 && yy < 128) {
                    const float4* src =
                        (const float4*)&x[((b * H_ + yy) * W_ + pms) * C_ + sth * 32];
                    #pragma unroll
                    for (int i = 0; i < 8; i++) {
                        float4 v = src[i];
                        dst[2*i]   = make_float2(v.x, v.y);
                        dst[2*i+1] = make_float2(v.z, v.w);
                    }
                } else {
                    #pragma unroll
                    for (int i = 0; i < 16; i++) dst[i] = make_float2(0.f, 0.f);
                }
            }
            __syncthreads();

            #pragma unroll
            for (int dx = 0; dx < 3; dx++) {
                const float* r0 = &row[(s      + dx) * 66 + q * 8];
                const float* r1 = &row[(s + 32 + dx) * 66 + q * 8];
                const float* r2 = &row[(s + 64 + dx) * 66 + q * 8];
                const float* r3 = &row[(s + 96 + dx) * 66 + q * 8];
                const unsigned long long* wq = wsh + dx * 640 + q * 80;
                #pragma unroll
                for (int c = 0; c < 8; c += 2) {
                    const float2 v0 = *(const float2*)&r0[c];
                    const float2 v1 = *(const float2*)&r1[c];
                    const float2 v2 = *(const float2*)&r2[c];
                    const float2 v3 = *(const float2*)&r3[c];
                    const unsigned long long* wx = wq + c * 10;
                    const unsigned long long* wy = wx + 10;
                    {
                        const unsigned long long a0 = pack2(v0.x, v0.x);
                        const unsigned long long a1 = pack2(v1.x, v1.x);
                        const unsigned long long a2 = pack2(v2.x, v2.x);
                        const unsigned long long a3 = pack2(v3.x, v3.x);
                        #pragma unroll
                        for (int p = 0; p < 9; p++) {
                            const unsigned long long w = wx[p];
                            ffma2(acc1[0][p], a0, w);
                            ffma2(acc1[1][p], a1, w);
                            ffma2(acc1[2][p], a2, w);
                            ffma2(acc1[3][p], a3, w);
                        }
                    }
                    {
                        const unsigned long long a0 = pack2(v0.y, v0.y);
                        const unsigned long long a1 = pack2(v1.y, v1.y);
                        const unsigned long long a2 = pack2(v2.y, v2.y);
                        const unsigned long long a3 = pack2(v3.y, v3.y);
                        #pragma unroll
                        for (int p = 0; p < 9; p++) {
                            const unsigned long long w = wy[p];
                            ffma2(acc1[0][p], a0, w);
                            ffma2(acc1[1][p], a1, w);
                            ffma2(acc1[2][p], a2, w);
                            ffma2(acc1[3][p], a3, w);
                        }
                    }
                }
            }
        }

        // cross-warp reduction (red in sm[0..), disjoint from off_sh)
        __syncthreads();
        unsigned long long* red = (unsigned long long*)sm;

        if (q >= 4) {
            #pragma unroll
            for (int r = 0; r < 4; r++)
                #pragma unroll
                for (int p = 0; p < 9; p++)
                    red[((q - 4) * 128 + s + r*32) * 9 + p] = acc1[r][p];
        }
        __syncthreads();
        if (q < 4) {
            #pragma unroll
            for (int r = 0; r < 4; r++)
                #pragma unroll
                for (int p = 0; p < 9; p++)
                    addf2(acc1[r][p], red[(q * 128 + s + r*32) * 9 + p]);
        }
        __syncthreads();
        if (q == 2 || q == 3) {
            #pragma unroll
            for (int r = 0; r < 4; r++)
                #pragma unroll
                for (int p = 0; p < 9; p++)
                    red[((q - 2) * 128 + s + r*32) * 9 + p] = acc1[r][p];
        }
        __syncthreads();
        if (q < 2) {
            #pragma unroll
            for (int r = 0; r < 4; r++)
                #pragma unroll
                for (int p = 0; p < 9; p++)
                    addf2(acc1[r][p], red[(q * 128 + s + r*32) * 9 + p]);
        }
        __syncthreads();
        if (q == 1) {
            #pragma unroll
            for (int r = 0; r < 4; r++)
                #pragma unroll
                for (int p = 0; p < 9; p++)
                    red[(s + r*32) * 9 + p] = acc1[r][p];
        }
        __syncthreads();
        if (q == 0) {
            #pragma unroll
            for (int r = 0; r < 4; r++) {
                const int px = s + r*32;
                float2* op = (float2*)&off_sh[px * 18];
                #pragma unroll
                for (int p = 0; p < 9; p++) {
                    addf2(acc1[r][p], red[px * 9 + p]);
                    float lo, hi;
                    asm("mov.b64 {%0,%1}, %2;" : "=f"(lo), "=f"(hi) : "l"(acc1[r][p]));
                    op[p] = make_float2(lo, hi);
                }
            }
        }
    }
    __syncthreads();   // offsets visible in smem; reduction area free

    // ======================= PHASE 2: sampling + GEMM =======================
    {
        float* Abuf[2] = { sm, sm + ABUFM };
        float* Bbuf[2] = { sm + 2*ABUFM, sm + 2*ABUFM + BBUF };
        const uint32_t Bu = smem_u32(sm + 2*ABUFM);

        const int wid  = tid >> 5;
        const int lane = tid & 31;
        const int g  = lane >> 2;
        const int tc = lane & 3;

        const int p0 = by * 128;
        const int b  = p0 >> 14;
        const int y  = (p0 >> 7) & 127;
        const int pm = tid & 127;
        const int h  = tid >> 7;

        const int m_base = (wid >> 2) * 32;
        const int n_base = (wid & 3) * 32;
        const float* offp = &off_sh[pm * 18];

        float acc[2][2][4][4];
        #pragma unroll
        for (int nf = 0; nf < 4; nf++) {
            const int c0 = n_base + nf*8 + 2*tc;
            const float bz0 = __ldg(&b_out[c0]), bz1 = __ldg(&b_out[c0+1]);
            #pragma unroll
            for (int sub = 0; sub < 2; sub++)
                #pragma unroll
                for (int mf = 0; mf < 2; mf++) {
                    acc[sub][mf][nf][0] = bz0; acc[sub][mf][nf][1] = bz1;
                    acc[sub][mf][nf][2] = bz0; acc[sub][mf][nf][3] = bz1;
                }
        }

        float wa=0.f, wbv=0.f, wcv=0.f, wdv=0.f;
        int i00=0, i10=0, i01=0, i11=0;

        #define COORDS(off) { \
            float nx = fminf(fmaxf((float)pm + (off).x, 0.f), 127.f); \
            float ny = fminf(fmaxf((float)y  + (off).y, 0.f), 127.f); \
            float x0f = floorf(nx), y0f = floorf(ny); \
            float x1f = fminf(x0f + 1.f, 127.f), y1f = fminf(y0f + 1.f, 127.f); \
            float lx = nx - x0f, hx = x1f - nx; \
            float ly = ny - y0f, hy = y1f - ny; \
            wa = hx*hy; wbv = hx*ly; wcv = lx*hy; wdv = lx*ly; \
            int ix0 = (int)x0f, ix1 = (int)x1f, iy0 = (int)y0f, iy1 = (int)y1f; \
            i00 = iy0*128 + ix0;  i10 = iy1*128 + ix0; \
            i01 = iy0*128 + ix1;  i11 = iy1*128 + ix1; }

        float4 ca, cb2, cc2, cd;

        #define GATHERPL(chv, j) { \
            const int cbp = (b*16 + ((chv)&1)*8 + h*4 + (j)) << 14; \
            ca  = g_xT[cbp + i00]; cb2 = g_xT[cbp + i10]; \
            cc2 = g_xT[cbp + i01]; cd  = g_xT[cbp + i11]; }

        // m-major A: one STS.128 per plane (4 consecutive k of pixel pm)
        #define WEIGHTSTS(j, Ab) { \
            const int kb = h*16 + (j)*4; \
            float4 vf; \
            vf.x = __uint_as_float(f2tf32(wa*ca.x + wbv*cb2.x + wcv*cc2.x + wdv*cd.x)); \
            vf.y = __uint_as_float(f2tf32(wa*ca.y + wbv*cb2.y + wcv*cc2.y + wdv*cd.y)); \
            vf.z = __uint_as_float(f2tf32(wa*ca.z + wbv*cb2.z + wcv*cc2.z + wdv*cd.z)); \
            vf.w = __uint_as_float(f2tf32(wa*ca.w + wbv*cb2.w + wcv*cc2.w + wdv*cd.w)); \
            *(float4*)&(Ab)[pm * SAM + kb] = vf; }

        #define CPB(chv, pbuf) { \
            const uint32_t dbase = Bu + (uint32_t)(pbuf) * (BBUF*4u); \
            const char* srcb = (const char*)&g_wTp[(chv) * BBUF]; \
            _Pragma("unroll") \
            for (int i = 0; i < 5; i++) { \
                int idx = tid + i*256; \
                if (idx < 1088) cpasync16(dbase + (uint32_t)idx*16u, srcb + idx*16); \
            } }

        #define MMAS(sstep, Ab, Bb) { \
            const int k0 = (sstep) * 8; \
            const uint32_t* Br0 = (const uint32_t*)&(Bb)[(k0 + tc)     * SB]; \
            const uint32_t* Br1 = (const uint32_t*)&(Bb)[(k0 + tc + 4) * SB]; \
            uint32_t bfr[4][2]; \
            _Pragma("unroll") \
            for (int nf = 0; nf < 4; nf++) { \
                const int n = n_base + nf*8 + g; \
                bfr[nf][0] = Br0[n];  bfr[nf][1] = Br1[n]; \
            } \
            const uint32_t* Au = (const uint32_t*)(Ab); \
            _Pragma("unroll") \
            for (int sub = 0; sub < 2; sub++) { \
                uint32_t afr[2][4]; \
                _Pragma("unroll") \
                for (int mf = 0; mf < 2; mf++) { \
                    const int m = sub*64 + m_base + mf*16 + g; \
                    afr[mf][0] = Au[(m)     * SAM + k0 + tc]; \
                    afr[mf][1] = Au[(m + 8) * SAM + k0 + tc]; \
                    afr[mf][2] = Au[(m)     * SAM + k0 + tc + 4]; \
                    afr[mf][3] = Au[(m + 8) * SAM + k0 + tc + 4]; \
                } \
                _Pragma("unroll") \
                for (int mf = 0; mf < 2; mf++) \
                    _Pragma("unroll") \
                    for (int nf = 0; nf < 4; nf++) \
                        mma_tf32(acc[sub][mf][nf], afr[mf], bfr[nf]); \
            } }

        float2 curoff  = *(const float2*)(offp + 0);
        float2 nextoff = *(const float2*)(offp + 2);
        COORDS(curoff);
        #pragma unroll
        for (int j = 0; j < 4; j++) {
            GATHERPL(0, j);
            WEIGHTSTS(j, Abuf[0]);
        }
        CPB(0, 0); CP_COMMIT();

        for (int ch = 0; ch < 18; ch++) {
            const int p = ch & 1;
            float* Ab = Abuf[p];
            float* Bb = Bbuf[p];
            float* An = Abuf[p ^ 1];

            CP_WAIT0();
            __syncthreads();

            const bool more = (ch + 1 < 18);
            if (more) {
                if (((ch + 1) & 1) == 0) {
                    COORDS(nextoff);
                    if (ch + 1 <= 14)
                        nextoff = *(const float2*)(offp + ((ch+3) >> 1) * 2);
                }
                GATHERPL(ch + 1, 0);
                CPB(ch + 1, p ^ 1); CP_COMMIT();
            }

            MMAS(0, Ab, Bb);
            if (more) { WEIGHTSTS(0, An); GATHERPL(ch + 1, 1); }
            MMAS(1, Ab, Bb);
            if (more) { WEIGHTSTS(1, An); GATHERPL(ch + 1, 2); }
            MMAS(2, Ab, Bb);
            if (more) { WEIGHTSTS(2, An); GATHERPL(ch + 1, 3); }
            MMAS(3, Ab, Bb);
            if (more) { WEIGHTSTS(3, An); }
        }

        #pragma unroll
        for (int sub = 0; sub < 2; sub++)
            #pragma unroll
            for (int mf = 0; mf < 2; mf++) {
                const int row = p0 + sub*64 + m_base + mf*16 + g;
                #pragma unroll
                for (int nf = 0; nf < 4; nf++) {
                    const int col = n_base + nf*8 + 2*tc;
                    *(float2*)&out[(size_t)row * F_ + col] =
                        make_float2(acc[sub][mf][nf][0], acc[sub][mf][nf][1]);
                    *(float2*)&out[(size_t)(row + 8) * F_ + col] =
                        make_float2(acc[sub][mf][nf][2], acc[sub][mf][nf][3]);
                }
            }
    }
}

// ---------------------------------------------------------------------------
extern "C" void kernel_launch(void* const* d_in, const int* in_sizes, int n_in,
                              void* d_out, int out_size)
{
    const float* x     = (const float*)d_in[0];
    const float* w_off = (const float*)d_in[1];
    const float* b_off = (const float*)d_in[2];
    const float* w_out = (const float*)d_in[3];
    const float* b_out = (const float*)d_in[4];
    float* out = (float*)d_out;

    cudaFuncSetAttribute(dconv_fused,
                         cudaFuncAttributeMaxDynamicSharedMemorySize, SM2_TOTAL);

    prep_fused <<<1353, 256>>>(w_out, w_off, (const float4*)x);
    dconv_fused<<<B_ * H_, 256, SM2_TOTAL>>>(x, b_off, b_out, out);
}